// round 12
// baseline (speedup 1.0000x reference)
#include <cuda_runtime.h>
#include <cuda_bf16.h>
#include <cstdint>

#define NN 10240
#define EE 160000

// Scratch (static device globals)
__device__ float g_Gf[(size_t)NN * 4096];   // G[n][kc][o][ki]: kc=k/4 (32), o (32), ki=k%4 (4); fp32, 167MB
__device__ float g_hb[NN * 32];
__device__ float g_Bperm[4096 * 32];        // Bperm[c'*32 + i], c' = kc*128 + o*4 + ki
__device__ float g_sum_ef[NN * 32];
__device__ float g_sum_tr[NN * 3];
__device__ int   g_cnt[NN];        // row-degree (mean)
__device__ int   g_deg[NN];        // col-degree (sort)
__device__ int   g_cur[NN];
// sorted edge data (by col)
__device__ int   g_srow[EE];
__device__ int   g_scol[EE];
__device__ float g_sea[(size_t)EE * 8];
__device__ float g_scd[(size_t)EE * 4];

// ---------------- zero ----------------
__global__ void zero_kernel(int N) {
    int i = blockIdx.x * blockDim.x + threadIdx.x;
    if (i < N * 32) g_sum_ef[i] = 0.f;
    if (i < N * 3)  g_sum_tr[i] = 0.f;
    if (i < N) { g_cnt[i] = 0; g_deg[i] = 0; }
}

// ---------------- permute Wk2 for the [kc][o][ki] G layout ----------------
// c' in [0,4096): kc = c'>>7, o = (c'>>2)&31, ki = c'&3; k = kc*4 + ki
__global__ void bperm_kernel(const float* __restrict__ Wk2) {
    int idx = blockIdx.x * blockDim.x + threadIdx.x;
    if (idx >= 4096 * 32) return;
    int i = idx & 31;
    int c = idx >> 5;
    int kc = c >> 7;
    int o  = (c >> 2) & 31;
    int ki = c & 3;
    int k  = kc * 4 + ki;
    g_Bperm[idx] = Wk2[k * 1024 + i * 32 + o];
}

// ---------------- hb = h @ bk2 ----------------
__global__ void hb_kernel(const float* __restrict__ h, const float* __restrict__ bk2, int N) {
    int warp = threadIdx.x >> 5, lane = threadIdx.x & 31;
    int n = blockIdx.x * 8 + warp;
    if (n >= N) return;
    float hv = h[n * 32 + lane];
    float acc = 0.f;
#pragma unroll
    for (int i = 0; i < 32; i++)
        acc = fmaf(__shfl_sync(0xffffffffu, hv, i), bk2[i * 32 + lane], acc);
    g_hb[n * 32 + lane] = acc;
}

// ---------------- G = H @ Bperm, fp32 out, 2 cols/thread ----------------
__global__ __launch_bounds__(256) void g_kernel(const float* __restrict__ h, int N) {
    __shared__ float hs[64 * 32];
    int n0 = blockIdx.x * 64;
    int c0 = (blockIdx.y * 256 + threadIdx.x) * 2;
    int lim = N * 32;
    for (int t = threadIdx.x; t < 64 * 32; t += 256) {
        int gi = n0 * 32 + t;
        hs[t] = (gi < lim) ? h[gi] : 0.f;
    }
    __syncthreads();
    float b0[32], b1[32];
#pragma unroll
    for (int q = 0; q < 8; q++) {
        float4 v0 = *reinterpret_cast<const float4*>(&g_Bperm[(size_t)c0 * 32 + q * 4]);
        float4 v1 = *reinterpret_cast<const float4*>(&g_Bperm[(size_t)(c0 + 1) * 32 + q * 4]);
        b0[q*4+0] = v0.x; b0[q*4+1] = v0.y; b0[q*4+2] = v0.z; b0[q*4+3] = v0.w;
        b1[q*4+0] = v1.x; b1[q*4+1] = v1.y; b1[q*4+2] = v1.z; b1[q*4+3] = v1.w;
    }
    int nmax = min(64, N - n0);
    for (int nn = 0; nn < nmax; nn++) {
        float a0 = 0.f, a1 = 0.f;
#pragma unroll
        for (int q = 0; q < 8; q++) {
            float4 hv = *reinterpret_cast<const float4*>(&hs[nn * 32 + q * 4]);
            a0 = fmaf(hv.x, b0[q*4+0], a0); a1 = fmaf(hv.x, b1[q*4+0], a1);
            a0 = fmaf(hv.y, b0[q*4+1], a0); a1 = fmaf(hv.y, b1[q*4+1], a1);
            a0 = fmaf(hv.z, b0[q*4+2], a0); a1 = fmaf(hv.z, b1[q*4+2], a1);
            a0 = fmaf(hv.w, b0[q*4+3], a0); a1 = fmaf(hv.w, b1[q*4+3], a1);
        }
        *reinterpret_cast<float2*>(&g_Gf[(size_t)(n0 + nn) * 4096 + c0]) =
            make_float2(a0, a1);
    }
}

// ---------------- histograms ----------------
__global__ void hist_kernel(const int* __restrict__ ei, int E) {
    int e = blockIdx.x * blockDim.x + threadIdx.x;
    if (e >= E) return;
    atomicAdd(&g_deg[ei[E + e]], 1);
    atomicAdd(&g_cnt[ei[e]], 1);
}

// ---------------- exclusive scan of col-degrees ----------------
__global__ void scan_kernel(int N) {
    __shared__ int s[1024];
    int tid = threadIdx.x;
    int base = tid * 10;
    int local[10];
    int sum = 0;
#pragma unroll
    for (int i = 0; i < 10; i++) {
        int idx = base + i;
        int v = (idx < N) ? g_deg[idx] : 0;
        local[i] = sum; sum += v;
    }
    s[tid] = sum;
    __syncthreads();
    for (int off = 1; off < 1024; off <<= 1) {
        int v = (tid >= off) ? s[tid - off] : 0;
        __syncthreads();
        s[tid] += v;
        __syncthreads();
    }
    int pre = (tid > 0) ? s[tid - 1] : 0;
#pragma unroll
    for (int i = 0; i < 10; i++) {
        int idx = base + i;
        if (idx < N) g_cur[idx] = pre + local[i];
    }
}

// ---------------- scatter: build fully sorted edge records ----------------
__global__ void scatter_kernel(const int* __restrict__ ei, const float* __restrict__ ea,
                               const float* __restrict__ coord, int E) {
    int e = blockIdx.x * blockDim.x + threadIdx.x;
    if (e >= E) return;
    int row = ei[e];
    int col = ei[E + e];
    int pos = atomicAdd(&g_cur[col], 1);
    g_srow[pos] = row;
    g_scol[pos] = col;
    float a0 = ea[e * 6 + 0], a1 = ea[e * 6 + 1], a2 = ea[e * 6 + 2];
    float a3 = ea[e * 6 + 3], a4 = ea[e * 6 + 4], a5 = ea[e * 6 + 5];
    float4* sp = reinterpret_cast<float4*>(&g_sea[(size_t)pos * 8]);
    sp[0] = make_float4(a0, a1, a2, a3);
    sp[1] = make_float4(a4, a5, 0.f, 0.f);
    float c0 = coord[row * 3 + 0] - coord[col * 3 + 0];
    float c1 = coord[row * 3 + 1] - coord[col * 3 + 1];
    float c2 = coord[row * 3 + 2] - coord[col * 3 + 2];
    *reinterpret_cast<float4*>(&g_scd[(size_t)pos * 4]) = make_float4(c0, c1, c2, 0.f);
}

// ---------------- edge kernel: 2 edges/warp-iter, fp32 coalesced gather ----------------
__global__ __launch_bounds__(256) void edge_kernel(
        const float* __restrict__ Wk1, const float* __restrict__ bk1,
        const float* __restrict__ Wc1, const float* __restrict__ bc1,
        const float* __restrict__ Wc2, int E) {
    __shared__ float sWk1[768], sbk1[128], sbc1[64], sWc2[64];
    __shared__ float2 sWc1p[1024];
    __shared__ float s_rz[8][2][128];
    __shared__ __align__(16) float s_ef[8][2][32];
    int tid = threadIdx.x;
    for (int t = tid; t < 768; t += 256)  sWk1[t] = Wk1[t];
    for (int t = tid; t < 1024; t += 256) {
        int o = t >> 5, l = t & 31;
        sWc1p[t] = make_float2(Wc1[o * 64 + l], Wc1[o * 64 + 32 + l]);
    }
    if (tid < 128) sbk1[tid] = bk1[tid];
    if (tid < 64)  sbc1[tid] = bc1[tid];
    if (tid < 64)  sWc2[tid] = Wc2[tid];
    __syncthreads();

    int warp = tid >> 5, lane = tid & 31;
    const unsigned FULL = 0xffffffffu;
    int per = (E + gridDim.x - 1) / gridDim.x;
    int j0 = blockIdx.x * per;
    int j1 = min(j0 + per, E);

    for (int j = j0 + warp * 2; j < j1; j += 16) {
        int jA = j;
        int jB = j + 1;
        bool vB = jB < j1;
        int row0 = g_srow[jA], col0 = g_scol[jA];
        int row1 = vB ? g_srow[jB] : row0;
        int col1 = vB ? g_scol[jB] : col0;

        float eaA = (lane < 6) ? g_sea[(size_t)jA * 8 + lane] : 0.f;
        float eaB = (vB && lane < 6) ? g_sea[(size_t)jB * 8 + lane] : 0.f;
        float a0A = __shfl_sync(FULL, eaA, 0), a1A = __shfl_sync(FULL, eaA, 1);
        float a2A = __shfl_sync(FULL, eaA, 2), a3A = __shfl_sync(FULL, eaA, 3);
        float a4A = __shfl_sync(FULL, eaA, 4), a5A = __shfl_sync(FULL, eaA, 5);
        float a0B = __shfl_sync(FULL, eaB, 0), a1B = __shfl_sync(FULL, eaB, 1);
        float a2B = __shfl_sync(FULL, eaB, 2), a3B = __shfl_sync(FULL, eaB, 3);
        float a4B = __shfl_sync(FULL, eaB, 4), a5B = __shfl_sync(FULL, eaB, 5);

        // rz = relu(ea @ Wk1 + bk1) for both edges; weight LDS shared
#pragma unroll
        for (int r = 0; r < 4; r++) {
            int k = r * 32 + lane;
            float w0 = sWk1[k], w1 = sWk1[128 + k], w2 = sWk1[256 + k];
            float w3 = sWk1[384 + k], w4 = sWk1[512 + k], w5 = sWk1[640 + k];
            float b = sbk1[k];
            float vA = b, vBv = b;
            vA = fmaf(a0A, w0, vA); vBv = fmaf(a0B, w0, vBv);
            vA = fmaf(a1A, w1, vA); vBv = fmaf(a1B, w1, vBv);
            vA = fmaf(a2A, w2, vA); vBv = fmaf(a2B, w2, vBv);
            vA = fmaf(a3A, w3, vA); vBv = fmaf(a3B, w3, vBv);
            vA = fmaf(a4A, w4, vA); vBv = fmaf(a4B, w4, vBv);
            vA = fmaf(a5A, w5, vA); vBv = fmaf(a5B, w5, vBv);
            s_rz[warp][0][k] = fmaxf(vA, 0.f);
            s_rz[warp][1][k] = fmaxf(vBv, 0.f);
        }
        __syncwarp();

        // ef = hb[col] + rz . G[col]: lane owns o=lane.
        // fp32 G layout [kc][o][ki4]: lane's 4 k-values at float4 index kc*32 + lane
        // -> consecutive lanes 16B apart: each LDG.128 covers 4 full lines.
        const float4* gp0 = reinterpret_cast<const float4*>(g_Gf) + (size_t)col0 * 1024 + lane;
        const float4* gp1 = reinterpret_cast<const float4*>(g_Gf) + (size_t)col1 * 1024 + lane;
        float acc0 = g_hb[col0 * 32 + lane], acc0b = 0.f;
        float acc1 = g_hb[col1 * 32 + lane], acc1b = 0.f;
#pragma unroll
        for (int kc = 0; kc < 16; kc++) {
            float4 gA0 = gp0[kc * 32];
            float4 gA1 = gp0[(kc + 16) * 32];
            float4 gB0 = gp1[kc * 32];
            float4 gB1 = gp1[(kc + 16) * 32];
            float4 rA0 = *reinterpret_cast<const float4*>(&s_rz[warp][0][kc * 4]);
            float4 rA1 = *reinterpret_cast<const float4*>(&s_rz[warp][0][(kc + 16) * 4]);
            float4 rB0 = *reinterpret_cast<const float4*>(&s_rz[warp][1][kc * 4]);
            float4 rB1 = *reinterpret_cast<const float4*>(&s_rz[warp][1][(kc + 16) * 4]);
            acc0  = fmaf(rA0.x, gA0.x, acc0);  acc0  = fmaf(rA0.y, gA0.y, acc0);
            acc0  = fmaf(rA0.z, gA0.z, acc0);  acc0  = fmaf(rA0.w, gA0.w, acc0);
            acc0b = fmaf(rA1.x, gA1.x, acc0b); acc0b = fmaf(rA1.y, gA1.y, acc0b);
            acc0b = fmaf(rA1.z, gA1.z, acc0b); acc0b = fmaf(rA1.w, gA1.w, acc0b);
            acc1  = fmaf(rB0.x, gB0.x, acc1);  acc1  = fmaf(rB0.y, gB0.y, acc1);
            acc1  = fmaf(rB0.z, gB0.z, acc1);  acc1  = fmaf(rB0.w, gB0.w, acc1);
            acc1b = fmaf(rB1.x, gB1.x, acc1b); acc1b = fmaf(rB1.y, gB1.y, acc1b);
            acc1b = fmaf(rB1.z, gB1.z, acc1b); acc1b = fmaf(rB1.w, gB1.w, acc1b);
        }
        acc0 += acc0b;
        acc1 += acc1b;

        // stash ef to smem; read back as float4 broadcasts for the coord MLP
        s_ef[warp][0][lane] = acc0;
        s_ef[warp][1][lane] = acc1;
        __syncwarp();

        float t0A = sbc1[lane], t1A = sbc1[32 + lane];
        float t0B = t0A, t1B = t1A;
#pragma unroll
        for (int q = 0; q < 8; q++) {
            float4 eA = *reinterpret_cast<const float4*>(&s_ef[warp][0][q * 4]);
            float4 eB = *reinterpret_cast<const float4*>(&s_ef[warp][1][q * 4]);
            float2 w0 = sWc1p[(q * 4 + 0) * 32 + lane];
            float2 w1 = sWc1p[(q * 4 + 1) * 32 + lane];
            float2 w2 = sWc1p[(q * 4 + 2) * 32 + lane];
            float2 w3 = sWc1p[(q * 4 + 3) * 32 + lane];
            t0A = fmaf(eA.x, w0.x, t0A); t1A = fmaf(eA.x, w0.y, t1A);
            t0B = fmaf(eB.x, w0.x, t0B); t1B = fmaf(eB.x, w0.y, t1B);
            t0A = fmaf(eA.y, w1.x, t0A); t1A = fmaf(eA.y, w1.y, t1A);
            t0B = fmaf(eB.y, w1.x, t0B); t1B = fmaf(eB.y, w1.y, t1B);
            t0A = fmaf(eA.z, w2.x, t0A); t1A = fmaf(eA.z, w2.y, t1A);
            t0B = fmaf(eB.z, w2.x, t0B); t1B = fmaf(eB.z, w2.y, t1B);
            t0A = fmaf(eA.w, w3.x, t0A); t1A = fmaf(eA.w, w3.y, t1A);
            t0B = fmaf(eB.w, w3.x, t0B); t1B = fmaf(eB.w, w3.y, t1B);
        }
        t0A = fmaxf(t0A, 0.f); t1A = fmaxf(t1A, 0.f);
        t0B = fmaxf(t0B, 0.f); t1B = fmaxf(t1B, 0.f);
        float wc2a = sWc2[lane], wc2b = sWc2[32 + lane];
        float pA = fmaf(t0A, wc2a, t1A * wc2b);
        float pB = fmaf(t0B, wc2a, t1B * wc2b);
#pragma unroll
        for (int off = 16; off; off >>= 1) {
            pA += __shfl_xor_sync(FULL, pA, off);
            pB += __shfl_xor_sync(FULL, pB, off);
        }

        atomicAdd(&g_sum_ef[row0 * 32 + lane], acc0);
        if (vB) atomicAdd(&g_sum_ef[row1 * 32 + lane], acc1);
        if (lane < 3) {
            float cdA = g_scd[(size_t)jA * 4 + lane];
            atomicAdd(&g_sum_tr[row0 * 3 + lane], cdA * pA);
            if (vB) {
                float cdB = g_scd[(size_t)jB * 4 + lane];
                atomicAdd(&g_sum_tr[row1 * 3 + lane], cdB * pB);
            }
        }
        __syncwarp();
    }
}

// ---------------- node epilogue ----------------
__global__ void node_kernel(const float* __restrict__ h, const float* __restrict__ coord,
                            const float* __restrict__ root, const float* __restrict__ bias,
                            float* __restrict__ out, int N) {
    int warp = threadIdx.x >> 5, lane = threadIdx.x & 31;
    int n = blockIdx.x * 8 + warp;
    if (n >= N) return;
    float hv = h[n * 32 + lane];
    float inv = 1.f / fmaxf((float)g_cnt[n], 1.f);
    float agg = g_sum_ef[n * 32 + lane] * inv + bias[lane];
#pragma unroll
    for (int i = 0; i < 32; i++)
        agg = fmaf(__shfl_sync(0xffffffffu, hv, i), root[i * 32 + lane], agg);
    out[n * 32 + lane] = hv + fmaxf(agg, 0.f) * 0.25f;
    if (lane < 3)
        out[N * 32 + n * 3 + lane] = g_sum_tr[n * 3 + lane] * inv * 0.25f + coord[n * 3 + lane];
}

extern "C" void kernel_launch(void* const* d_in, const int* in_sizes, int n_in,
                              void* d_out, int out_size) {
    const float* h     = (const float*)d_in[0];
    const int*   ei    = (const int*)  d_in[1];
    const float* coord = (const float*)d_in[2];
    const float* ea    = (const float*)d_in[3];
    const float* Wk1   = (const float*)d_in[4];
    const float* bk1   = (const float*)d_in[5];
    const float* Wk2   = (const float*)d_in[6];
    const float* bk2   = (const float*)d_in[7];
    const float* root  = (const float*)d_in[8];
    const float* bias  = (const float*)d_in[9];
    const float* Wc1   = (const float*)d_in[10];
    const float* bc1   = (const float*)d_in[11];
    const float* Wc2   = (const float*)d_in[12];

    int N = in_sizes[0] / 32;
    int E = in_sizes[1] / 2;
    float* out = (float*)d_out;

    zero_kernel<<<(N * 32 + 255) / 256, 256>>>(N);
    bperm_kernel<<<(4096 * 32 + 255) / 256, 256>>>(Wk2);
    hb_kernel<<<(N + 7) / 8, 256>>>(h, bk2, N);
    dim3 gg((N + 63) / 64, 8);
    g_kernel<<<gg, 256>>>(h, N);
    hist_kernel<<<(E + 255) / 256, 256>>>(ei, E);
    scan_kernel<<<1, 1024>>>(N);
    scatter_kernel<<<(E + 255) / 256, 256>>>(ei, ea, coord, E);
    edge_kernel<<<592, 256>>>(Wk1, bk1, Wc1, bc1, Wc2, E);
    node_kernel<<<(N + 7) / 8, 256>>>(h, coord, root, bias, out, N);
}

// round 13
// speedup vs baseline: 1.2828x; 1.2828x over previous
#include <cuda_runtime.h>
#include <cuda_bf16.h>
#include <cstdint>

#define NN 10240
#define EE 160000

// Scratch (static device globals)
__device__ __nv_bfloat16 g_G[(size_t)NN * 4096];   // G[n][kb][o][ki]: kb=k/8 (16), o (32), ki=k%8 (8)
__device__ float g_hb[NN * 32];
__device__ float g_Bperm[4096 * 32];
__device__ float g_sum_ef[NN * 32];
__device__ float g_sum_tr[NN * 3];
__device__ int   g_cnt[NN];        // row-degree (mean)
__device__ int   g_deg[NN];        // col-degree (sort)
__device__ int   g_cur[NN];
// sorted edge data (by col)
__device__ int   g_srow[EE];
__device__ int   g_scol[EE];
__device__ float g_sea[(size_t)EE * 8];
__device__ float g_scd[(size_t)EE * 4];

// ---------------- zero ----------------
__global__ void zero_kernel(int N) {
    int i = blockIdx.x * blockDim.x + threadIdx.x;
    if (i < N * 32) g_sum_ef[i] = 0.f;
    if (i < N * 3)  g_sum_tr[i] = 0.f;
    if (i < N) { g_cnt[i] = 0; g_deg[i] = 0; }
}

// ---------------- permute Wk2 for the [kb][o][ki] G layout ----------------
__global__ void bperm_kernel(const float* __restrict__ Wk2) {
    int idx = blockIdx.x * blockDim.x + threadIdx.x;
    if (idx >= 4096 * 32) return;
    int i = idx & 31;
    int c = idx >> 5;
    int kb = c >> 8;
    int o  = (c >> 3) & 31;
    int ki = c & 7;
    int k  = kb * 8 + ki;
    g_Bperm[idx] = Wk2[k * 1024 + i * 32 + o];
}

// ---------------- hb = h @ bk2 ----------------
__global__ void hb_kernel(const float* __restrict__ h, const float* __restrict__ bk2, int N) {
    int warp = threadIdx.x >> 5, lane = threadIdx.x & 31;
    int n = blockIdx.x * 8 + warp;
    if (n >= N) return;
    float hv = h[n * 32 + lane];
    float acc = 0.f;
#pragma unroll
    for (int i = 0; i < 32; i++)
        acc = fmaf(__shfl_sync(0xffffffffu, hv, i), bk2[i * 32 + lane], acc);
    g_hb[n * 32 + lane] = acc;
}

// ---------------- G = H @ Bperm, bf16, 2 cols/thread (R5/R9 proven) ----------------
__global__ __launch_bounds__(256) void g_kernel(const float* __restrict__ h, int N) {
    __shared__ float hs[64 * 32];
    int n0 = blockIdx.x * 64;
    int c0 = (blockIdx.y * 256 + threadIdx.x) * 2;
    int lim = N * 32;
    for (int t = threadIdx.x; t < 64 * 32; t += 256) {
        int gi = n0 * 32 + t;
        hs[t] = (gi < lim) ? h[gi] : 0.f;
    }
    __syncthreads();
    float b0[32], b1[32];
#pragma unroll
    for (int q = 0; q < 8; q++) {
        float4 v0 = *reinterpret_cast<const float4*>(&g_Bperm[(size_t)c0 * 32 + q * 4]);
        float4 v1 = *reinterpret_cast<const float4*>(&g_Bperm[(size_t)(c0 + 1) * 32 + q * 4]);
        b0[q*4+0] = v0.x; b0[q*4+1] = v0.y; b0[q*4+2] = v0.z; b0[q*4+3] = v0.w;
        b1[q*4+0] = v1.x; b1[q*4+1] = v1.y; b1[q*4+2] = v1.z; b1[q*4+3] = v1.w;
    }
    int nmax = min(64, N - n0);
    for (int nn = 0; nn < nmax; nn++) {
        float a0 = 0.f, a1 = 0.f;
#pragma unroll
        for (int q = 0; q < 8; q++) {
            float4 hv = *reinterpret_cast<const float4*>(&hs[nn * 32 + q * 4]);
            a0 = fmaf(hv.x, b0[q*4+0], a0); a1 = fmaf(hv.x, b1[q*4+0], a1);
            a0 = fmaf(hv.y, b0[q*4+1], a0); a1 = fmaf(hv.y, b1[q*4+1], a1);
            a0 = fmaf(hv.z, b0[q*4+2], a0); a1 = fmaf(hv.z, b1[q*4+2], a1);
            a0 = fmaf(hv.w, b0[q*4+3], a0); a1 = fmaf(hv.w, b1[q*4+3], a1);
        }
        *reinterpret_cast<__nv_bfloat162*>(&g_G[(size_t)(n0 + nn) * 4096 + c0]) =
            __floats2bfloat162_rn(a0, a1);
    }
}

// ---------------- histograms ----------------
__global__ void hist_kernel(const int* __restrict__ ei, int E) {
    int e = blockIdx.x * blockDim.x + threadIdx.x;
    if (e >= E) return;
    atomicAdd(&g_deg[ei[E + e]], 1);
    atomicAdd(&g_cnt[ei[e]], 1);
}

// ---------------- exclusive scan of col-degrees ----------------
__global__ void scan_kernel(int N) {
    __shared__ int s[1024];
    int tid = threadIdx.x;
    int base = tid * 10;
    int local[10];
    int sum = 0;
#pragma unroll
    for (int i = 0; i < 10; i++) {
        int idx = base + i;
        int v = (idx < N) ? g_deg[idx] : 0;
        local[i] = sum; sum += v;
    }
    s[tid] = sum;
    __syncthreads();
    for (int off = 1; off < 1024; off <<= 1) {
        int v = (tid >= off) ? s[tid - off] : 0;
        __syncthreads();
        s[tid] += v;
        __syncthreads();
    }
    int pre = (tid > 0) ? s[tid - 1] : 0;
#pragma unroll
    for (int i = 0; i < 10; i++) {
        int idx = base + i;
        if (idx < N) g_cur[idx] = pre + local[i];
    }
}

// ---------------- scatter: build fully sorted edge records ----------------
__global__ void scatter_kernel(const int* __restrict__ ei, const float* __restrict__ ea,
                               const float* __restrict__ coord, int E) {
    int e = blockIdx.x * blockDim.x + threadIdx.x;
    if (e >= E) return;
    int row = ei[e];
    int col = ei[E + e];
    int pos = atomicAdd(&g_cur[col], 1);
    g_srow[pos] = row;
    g_scol[pos] = col;
    float a0 = ea[e * 6 + 0], a1 = ea[e * 6 + 1], a2 = ea[e * 6 + 2];
    float a3 = ea[e * 6 + 3], a4 = ea[e * 6 + 4], a5 = ea[e * 6 + 5];
    float4* sp = reinterpret_cast<float4*>(&g_sea[(size_t)pos * 8]);
    sp[0] = make_float4(a0, a1, a2, a3);
    sp[1] = make_float4(a4, a5, 0.f, 0.f);
    float c0 = coord[row * 3 + 0] - coord[col * 3 + 0];
    float c1 = coord[row * 3 + 1] - coord[col * 3 + 1];
    float c2 = coord[row * 3 + 2] - coord[col * 3 + 2];
    *reinterpret_cast<float4*>(&g_scd[(size_t)pos * 4]) = make_float4(c0, c1, c2, 0.f);
}

// ---------------- edge kernel: 2 edges/warp-iter, col-dedup gather ----------------
__global__ __launch_bounds__(256) void edge_kernel(
        const float* __restrict__ Wk1, const float* __restrict__ bk1,
        const float* __restrict__ Wc1, const float* __restrict__ bc1,
        const float* __restrict__ Wc2, int E) {
    __shared__ float sWk1[768], sbk1[128], sbc1[64], sWc2[64];
    __shared__ float2 sWc1p[1024];
    __shared__ float s_rz[8][2][128];
    __shared__ __align__(16) float s_ef[8][2][32];
    int tid = threadIdx.x;
    for (int t = tid; t < 768; t += 256)  sWk1[t] = Wk1[t];
    for (int t = tid; t < 1024; t += 256) {
        int o = t >> 5, l = t & 31;
        sWc1p[t] = make_float2(Wc1[o * 64 + l], Wc1[o * 64 + 32 + l]);
    }
    if (tid < 128) sbk1[tid] = bk1[tid];
    if (tid < 64)  sbc1[tid] = bc1[tid];
    if (tid < 64)  sWc2[tid] = Wc2[tid];
    __syncthreads();

    int warp = tid >> 5, lane = tid & 31;
    const unsigned FULL = 0xffffffffu;
    int per = (E + gridDim.x - 1) / gridDim.x;
    int j0 = blockIdx.x * per;
    int j1 = min(j0 + per, E);

    for (int j = j0 + warp * 2; j < j1; j += 16) {
        int jA = j;
        int jB = j + 1;
        bool vB = jB < j1;
        int row0 = g_srow[jA], col0 = g_scol[jA];
        int row1 = vB ? g_srow[jB] : row0;
        int col1 = vB ? g_scol[jB] : col0;

        float eaA = (lane < 6) ? g_sea[(size_t)jA * 8 + lane] : 0.f;
        float eaB = (vB && lane < 6) ? g_sea[(size_t)jB * 8 + lane] : 0.f;
        float a0A = __shfl_sync(FULL, eaA, 0), a1A = __shfl_sync(FULL, eaA, 1);
        float a2A = __shfl_sync(FULL, eaA, 2), a3A = __shfl_sync(FULL, eaA, 3);
        float a4A = __shfl_sync(FULL, eaA, 4), a5A = __shfl_sync(FULL, eaA, 5);
        float a0B = __shfl_sync(FULL, eaB, 0), a1B = __shfl_sync(FULL, eaB, 1);
        float a2B = __shfl_sync(FULL, eaB, 2), a3B = __shfl_sync(FULL, eaB, 3);
        float a4B = __shfl_sync(FULL, eaB, 4), a5B = __shfl_sync(FULL, eaB, 5);

        // rz = relu(ea @ Wk1 + bk1) for both edges; weight LDS shared
#pragma unroll
        for (int r = 0; r < 4; r++) {
            int k = r * 32 + lane;
            float w0 = sWk1[k], w1 = sWk1[128 + k], w2 = sWk1[256 + k];
            float w3 = sWk1[384 + k], w4 = sWk1[512 + k], w5 = sWk1[640 + k];
            float b = sbk1[k];
            float vA = b, vBv = b;
            vA = fmaf(a0A, w0, vA); vBv = fmaf(a0B, w0, vBv);
            vA = fmaf(a1A, w1, vA); vBv = fmaf(a1B, w1, vBv);
            vA = fmaf(a2A, w2, vA); vBv = fmaf(a2B, w2, vBv);
            vA = fmaf(a3A, w3, vA); vBv = fmaf(a3B, w3, vBv);
            vA = fmaf(a4A, w4, vA); vBv = fmaf(a4B, w4, vBv);
            vA = fmaf(a5A, w5, vA); vBv = fmaf(a5B, w5, vBv);
            s_rz[warp][0][k] = fmaxf(vA, 0.f);
            s_rz[warp][1][k] = fmaxf(vBv, 0.f);
        }
        __syncwarp();

        // ef = hb[col] + rz . G[col]: lane owns o=lane.
        // G layout [kb][o][ki]: lane's 8 k-values at elem offset kb*256 + lane*8.
        // Sorted pairs share col ~94% of the time -> warp-uniform dedup branch.
        float acc0 = g_hb[col0 * 32 + lane];
        float acc1;
        const __nv_bfloat16* gp0 = g_G + (size_t)col0 * 4096 + lane * 8;
        if (col1 == col0) {
            acc1 = acc0;
#pragma unroll
            for (int kc = 0; kc < 16; kc++) {
                uint4 gv = *reinterpret_cast<const uint4*>(gp0 + kc * 256);
                float4 ra0 = *reinterpret_cast<const float4*>(&s_rz[warp][0][kc * 8]);
                float4 rb0 = *reinterpret_cast<const float4*>(&s_rz[warp][0][kc * 8 + 4]);
                float4 ra1 = *reinterpret_cast<const float4*>(&s_rz[warp][1][kc * 8]);
                float4 rb1 = *reinterpret_cast<const float4*>(&s_rz[warp][1][kc * 8 + 4]);
                float2 f0 = __bfloat1622float2(*reinterpret_cast<const __nv_bfloat162*>(&gv.x));
                float2 f1 = __bfloat1622float2(*reinterpret_cast<const __nv_bfloat162*>(&gv.y));
                float2 f2 = __bfloat1622float2(*reinterpret_cast<const __nv_bfloat162*>(&gv.z));
                float2 f3 = __bfloat1622float2(*reinterpret_cast<const __nv_bfloat162*>(&gv.w));
                acc0 = fmaf(ra0.x, f0.x, acc0); acc1 = fmaf(ra1.x, f0.x, acc1);
                acc0 = fmaf(ra0.y, f0.y, acc0); acc1 = fmaf(ra1.y, f0.y, acc1);
                acc0 = fmaf(ra0.z, f1.x, acc0); acc1 = fmaf(ra1.z, f1.x, acc1);
                acc0 = fmaf(ra0.w, f1.y, acc0); acc1 = fmaf(ra1.w, f1.y, acc1);
                acc0 = fmaf(rb0.x, f2.x, acc0); acc1 = fmaf(rb1.x, f2.x, acc1);
                acc0 = fmaf(rb0.y, f2.y, acc0); acc1 = fmaf(rb1.y, f2.y, acc1);
                acc0 = fmaf(rb0.z, f3.x, acc0); acc1 = fmaf(rb1.z, f3.x, acc1);
                acc0 = fmaf(rb0.w, f3.y, acc0); acc1 = fmaf(rb1.w, f3.y, acc1);
            }
        } else {
            const __nv_bfloat16* gp1 = g_G + (size_t)col1 * 4096 + lane * 8;
            acc1 = g_hb[col1 * 32 + lane];
#pragma unroll
            for (int kc = 0; kc < 16; kc++) {
                uint4 gv0 = *reinterpret_cast<const uint4*>(gp0 + kc * 256);
                uint4 gv1 = *reinterpret_cast<const uint4*>(gp1 + kc * 256);
                float4 ra0 = *reinterpret_cast<const float4*>(&s_rz[warp][0][kc * 8]);
                float4 rb0 = *reinterpret_cast<const float4*>(&s_rz[warp][0][kc * 8 + 4]);
                float4 ra1 = *reinterpret_cast<const float4*>(&s_rz[warp][1][kc * 8]);
                float4 rb1 = *reinterpret_cast<const float4*>(&s_rz[warp][1][kc * 8 + 4]);
                float2 f;
                f = __bfloat1622float2(*reinterpret_cast<const __nv_bfloat162*>(&gv0.x));
                acc0 = fmaf(ra0.x, f.x, acc0); acc0 = fmaf(ra0.y, f.y, acc0);
                f = __bfloat1622float2(*reinterpret_cast<const __nv_bfloat162*>(&gv0.y));
                acc0 = fmaf(ra0.z, f.x, acc0); acc0 = fmaf(ra0.w, f.y, acc0);
                f = __bfloat1622float2(*reinterpret_cast<const __nv_bfloat162*>(&gv0.z));
                acc0 = fmaf(rb0.x, f.x, acc0); acc0 = fmaf(rb0.y, f.y, acc0);
                f = __bfloat1622float2(*reinterpret_cast<const __nv_bfloat162*>(&gv0.w));
                acc0 = fmaf(rb0.z, f.x, acc0); acc0 = fmaf(rb0.w, f.y, acc0);
                f = __bfloat1622float2(*reinterpret_cast<const __nv_bfloat162*>(&gv1.x));
                acc1 = fmaf(ra1.x, f.x, acc1); acc1 = fmaf(ra1.y, f.y, acc1);
                f = __bfloat1622float2(*reinterpret_cast<const __nv_bfloat162*>(&gv1.y));
                acc1 = fmaf(ra1.z, f.x, acc1); acc1 = fmaf(ra1.w, f.y, acc1);
                f = __bfloat1622float2(*reinterpret_cast<const __nv_bfloat162*>(&gv1.z));
                acc1 = fmaf(rb1.x, f.x, acc1); acc1 = fmaf(rb1.y, f.y, acc1);
                f = __bfloat1622float2(*reinterpret_cast<const __nv_bfloat162*>(&gv1.w));
                acc1 = fmaf(rb1.z, f.x, acc1); acc1 = fmaf(rb1.w, f.y, acc1);
            }
        }

        // stash ef to smem; read back as float4 broadcasts for the coord MLP
        s_ef[warp][0][lane] = acc0;
        s_ef[warp][1][lane] = acc1;
        __syncwarp();

        float t0A = sbc1[lane], t1A = sbc1[32 + lane];
        float t0B = t0A, t1B = t1A;
#pragma unroll
        for (int q = 0; q < 8; q++) {
            float4 eA = *reinterpret_cast<const float4*>(&s_ef[warp][0][q * 4]);
            float4 eB = *reinterpret_cast<const float4*>(&s_ef[warp][1][q * 4]);
            float2 w0 = sWc1p[(q * 4 + 0) * 32 + lane];
            float2 w1 = sWc1p[(q * 4 + 1) * 32 + lane];
            float2 w2 = sWc1p[(q * 4 + 2) * 32 + lane];
            float2 w3 = sWc1p[(q * 4 + 3) * 32 + lane];
            t0A = fmaf(eA.x, w0.x, t0A); t1A = fmaf(eA.x, w0.y, t1A);
            t0B = fmaf(eB.x, w0.x, t0B); t1B = fmaf(eB.x, w0.y, t1B);
            t0A = fmaf(eA.y, w1.x, t0A); t1A = fmaf(eA.y, w1.y, t1A);
            t0B = fmaf(eB.y, w1.x, t0B); t1B = fmaf(eB.y, w1.y, t1B);
            t0A = fmaf(eA.z, w2.x, t0A); t1A = fmaf(eA.z, w2.y, t1A);
            t0B = fmaf(eB.z, w2.x, t0B); t1B = fmaf(eB.z, w2.y, t1B);
            t0A = fmaf(eA.w, w3.x, t0A); t1A = fmaf(eA.w, w3.y, t1A);
            t0B = fmaf(eB.w, w3.x, t0B); t1B = fmaf(eB.w, w3.y, t1B);
        }
        t0A = fmaxf(t0A, 0.f); t1A = fmaxf(t1A, 0.f);
        t0B = fmaxf(t0B, 0.f); t1B = fmaxf(t1B, 0.f);
        float wc2a = sWc2[lane], wc2b = sWc2[32 + lane];
        float pA = fmaf(t0A, wc2a, t1A * wc2b);
        float pB = fmaf(t0B, wc2a, t1B * wc2b);
#pragma unroll
        for (int off = 16; off; off >>= 1) {
            pA += __shfl_xor_sync(FULL, pA, off);
            pB += __shfl_xor_sync(FULL, pB, off);
        }

        atomicAdd(&g_sum_ef[row0 * 32 + lane], acc0);
        if (vB) atomicAdd(&g_sum_ef[row1 * 32 + lane], acc1);
        if (lane < 3) {
            float cdA = g_scd[(size_t)jA * 4 + lane];
            atomicAdd(&g_sum_tr[row0 * 3 + lane], cdA * pA);
            if (vB) {
                float cdB = g_scd[(size_t)jB * 4 + lane];
                atomicAdd(&g_sum_tr[row1 * 3 + lane], cdB * pB);
            }
        }
        __syncwarp();
    }
}

// ---------------- node epilogue ----------------
__global__ void node_kernel(const float* __restrict__ h, const float* __restrict__ coord,
                            const float* __restrict__ root, const float* __restrict__ bias,
                            float* __restrict__ out, int N) {
    int warp = threadIdx.x >> 5, lane = threadIdx.x & 31;
    int n = blockIdx.x * 8 + warp;
    if (n >= N) return;
    float hv = h[n * 32 + lane];
    float inv = 1.f / fmaxf((float)g_cnt[n], 1.f);
    float agg = g_sum_ef[n * 32 + lane] * inv + bias[lane];
#pragma unroll
    for (int i = 0; i < 32; i++)
        agg = fmaf(__shfl_sync(0xffffffffu, hv, i), root[i * 32 + lane], agg);
    out[n * 32 + lane] = hv + fmaxf(agg, 0.f) * 0.25f;
    if (lane < 3)
        out[N * 32 + n * 3 + lane] = g_sum_tr[n * 3 + lane] * inv * 0.25f + coord[n * 3 + lane];
}

extern "C" void kernel_launch(void* const* d_in, const int* in_sizes, int n_in,
                              void* d_out, int out_size) {
    const float* h     = (const float*)d_in[0];
    const int*   ei    = (const int*)  d_in[1];
    const float* coord = (const float*)d_in[2];
    const float* ea    = (const float*)d_in[3];
    const float* Wk1   = (const float*)d_in[4];
    const float* bk1   = (const float*)d_in[5];
    const float* Wk2   = (const float*)d_in[6];
    const float* bk2   = (const float*)d_in[7];
    const float* root  = (const float*)d_in[8];
    const float* bias  = (const float*)d_in[9];
    const float* Wc1   = (const float*)d_in[10];
    const float* bc1   = (const float*)d_in[11];
    const float* Wc2   = (const float*)d_in[12];

    int N = in_sizes[0] / 32;
    int E = in_sizes[1] / 2;
    float* out = (float*)d_out;

    zero_kernel<<<(N * 32 + 255) / 256, 256>>>(N);
    bperm_kernel<<<(4096 * 32 + 255) / 256, 256>>>(Wk2);
    hb_kernel<<<(N + 7) / 8, 256>>>(h, bk2, N);
    dim3 gg((N + 63) / 64, 8);
    g_kernel<<<gg, 256>>>(h, N);
    hist_kernel<<<(E + 255) / 256, 256>>>(ei, E);
    scan_kernel<<<1, 1024>>>(N);
    scatter_kernel<<<(E + 255) / 256, 256>>>(ei, ea, coord, E);
    edge_kernel<<<592, 256>>>(Wk1, bk1, Wc1, bc1, Wc2, E);
    node_kernel<<<(N + 7) / 8, 256>>>(h, coord, root, bias, out, N);
}